// round 13
// baseline (speedup 1.0000x reference)
#include <cuda_runtime.h>
#include <cuda_bf16.h>
#include <cstdint>

// CALayer SE, single-pass persistent kernel: depth-2 pipelined gates +
// merged read/write loop (reads of batch b overlap stores of batch b-2).
// 1024 co-resident blocks (LB(256,7): 7x148=1036 slots); each owns a
// quarter-plane (16KB) per batch.
//   prologue: read_sum(0), read_sum(1)
//   round b (2..15): gate_mlp(b-2)  [spin~0: 2 rounds of slack]
//                    merged: load b (.ca), load b-2 (L2 hit), scale, st.cs,
//                            sum b, publish counter(b)
//   tail: gate_mlp(14), scale(14), gate_mlp(15), scale(15)
// Counters self-reset (single kernel launch). DRAM traffic = 537MB.

#define BATCH 16
#define CHAN 256
#define CR 16
#define HW 16384               // floats per plane
#define PLANE_F4 (HW/4)        // 4096
#define QF4 (PLANE_F4/4)       // 1024 float4 per quarter chunk
#define NBLK 1024
#define TPB 256

__device__ float g_part[BATCH * CHAN * 4];
__device__ int   g_cnt[BATCH];
__device__ int   g_done[BATCH];

__device__ __forceinline__ void stcs4(float4* p, float4 v) {
    asm volatile("st.global.cs.v4.f32 [%0], {%1,%2,%3,%4};"
                 :: "l"(p), "f"(v.x), "f"(v.y), "f"(v.z), "f"(v.w) : "memory");
}
__device__ __forceinline__ float4 ldcg4(const float4* p) {
    float4 v;
    asm volatile("ld.global.cg.v4.f32 {%0,%1,%2,%3}, [%4];"
                 : "=f"(v.x), "=f"(v.y), "=f"(v.z), "=f"(v.w) : "l"(p));
    return v;
}

__global__ __launch_bounds__(TPB, 7) void fused_se_kernel(
    const float* __restrict__ x, float* __restrict__ out,
    const float* __restrict__ w1, const float* __restrict__ b1,
    const float* __restrict__ w2, const float* __restrict__ b2)
{
    __shared__ float sred[8];
    __shared__ float smean[CHAN];
    __shared__ float shid[CR];
    __shared__ float sscale;

    const int chan    = blockIdx.x >> 2;   // 0..255
    const int quarter = blockIdx.x & 3;    // 0..3
    const int tid  = threadIdx.x;
    const int lane = tid & 31;
    const int wid  = tid >> 5;
    const size_t qoff = (size_t)quarter * QF4;

    const float4* __restrict__ x4 = reinterpret_cast<const float4*>(x);
    float4* __restrict__ o4 = reinterpret_cast<float4*>(out);

    auto chunk = [&](int b) {
        return x4 + (size_t)((b << 8) | chan) * PLANE_F4 + qoff;
    };
    auto ochunk = [&](int b) {
        return o4 + (size_t)((b << 8) | chan) * PLANE_F4 + qoff;
    };

    // block-reduce acc, publish partial for batch b
    auto publish = [&](int b, float acc) {
        #pragma unroll
        for (int o = 16; o; o >>= 1) acc += __shfl_xor_sync(0xFFFFFFFF, acc, o);
        if (lane == 0) sred[wid] = acc;
        __syncthreads();
        if (tid == 0) {
            float t = 0.f;
            #pragma unroll
            for (int w = 0; w < 8; w++) t += sred[w];
            g_part[((((b << 8) | chan)) << 2) + quarter] = t;
            __threadfence();
            atomicAdd(&g_cnt[b], 1);
        }
        __syncthreads();
    };

    auto read_sum = [&](int b) {
        const float4* __restrict__ xp = chunk(b);
        float acc = 0.f;
        #pragma unroll
        for (int i = 0; i < 4; i++) {
            float4 v = xp[tid + i * TPB];          // .ca -> L2 resident
            acc += (v.x + v.y) + (v.z + v.w);
        }
        publish(b, acc);
    };

    // gate on batch b's counter, compute means + MLP -> sscale
    auto gate_mlp = [&](int b) {
        if (tid == 0) {
            while (atomicAdd(&g_cnt[b], 0) < NBLK) __nanosleep(64);
            __threadfence();
            if (atomicAdd(&g_done[b], 1) == NBLK - 1) {  // last one resets
                atomicExch(&g_cnt[b], 0);
                atomicExch(&g_done[b], 0);
            }
        }
        __syncthreads();
        {
            const int q = ((b << 8) + tid) * 4;
            smean[tid] = (__ldcg(&g_part[q]) + __ldcg(&g_part[q + 1]) +
                          __ldcg(&g_part[q + 2]) + __ldcg(&g_part[q + 3])) * (1.0f / HW);
        }
        __syncthreads();
        #pragma unroll
        for (int k = 0; k < 2; k++) {
            const int r = wid * 2 + k;
            float acc = 0.f;
            #pragma unroll
            for (int c = lane; c < CHAN; c += 32)
                acc += __ldg(&w1[r * CHAN + c]) * smean[c];
            #pragma unroll
            for (int o = 16; o; o >>= 1) acc += __shfl_xor_sync(0xFFFFFFFF, acc, o);
            if (lane == 0) shid[r] = fmaxf(acc + __ldg(&b1[r]), 0.f);
        }
        __syncthreads();
        if (tid == 0) {
            float acc = __ldg(&b2[chan]);
            #pragma unroll
            for (int r = 0; r < CR; r++)
                acc += __ldg(&w2[chan * CR + r]) * shid[r];
            sscale = 1.0f / (1.0f + __expf(-acc));
        }
        __syncthreads();
    };

    // read+sum batch b (DRAM) while scaling+storing batch bs (L2 hits)
    auto merged = [&](int b, int bs) {
        const float sc = sscale;
        const float4* __restrict__ xb = chunk(b);
        const float4* __restrict__ xs = chunk(bs);
        float4* __restrict__ os = ochunk(bs);
        float acc = 0.f;
        #pragma unroll
        for (int i = 0; i < 4; i++) {
            const int idx = tid + i * TPB;
            float4 v = xb[idx];                    // DRAM read (.ca)
            float4 w = ldcg4(&xs[idx]);            // L2 hit (2 rounds old)
            w.x *= sc; w.y *= sc; w.z *= sc; w.w *= sc;
            stcs4(&os[idx], w);                    // streaming write
            acc += (v.x + v.y) + (v.z + v.w);
        }
        publish(b, acc);
    };

    // scale+store batch b only (tail)
    auto scale_only = [&](int b) {
        const float sc = sscale;
        const float4* __restrict__ xs = chunk(b);
        float4* __restrict__ os = ochunk(b);
        #pragma unroll
        for (int i = 0; i < 4; i++) {
            const int idx = tid + i * TPB;
            float4 w = ldcg4(&xs[idx]);
            w.x *= sc; w.y *= sc; w.z *= sc; w.w *= sc;
            stcs4(&os[idx], w);
        }
        __syncthreads();
    };

    // ---------- depth-2 pipelined main loop ----------
    read_sum(0);
    read_sum(1);
    for (int b = 2; b < BATCH; b++) {
        gate_mlp(b - 2);       // ~zero spin: published 2 rounds ago
        merged(b, b - 2);      // read b overlaps write b-2
    }
    gate_mlp(BATCH - 2);
    scale_only(BATCH - 2);
    gate_mlp(BATCH - 1);
    scale_only(BATCH - 1);
}

extern "C" void kernel_launch(void* const* d_in, const int* in_sizes, int n_in,
                              void* d_out, int out_size) {
    const float* x  = (const float*)d_in[0];
    const float* w1 = (const float*)d_in[1];
    const float* b1 = (const float*)d_in[2];
    const float* w2 = (const float*)d_in[3];
    const float* b2 = (const float*)d_in[4];
    float* out = (float*)d_out;

    fused_se_kernel<<<NBLK, TPB>>>(x, out, w1, b1, w2, b2);
}